// round 3
// baseline (speedup 1.0000x reference)
#include <cuda_runtime.h>
#include <math_constants.h>

#define BB 2
#define NN 32768
#define MM 4096
#define M2 (MM / 2)
#define CC 128
#define OUTC 128
#define INC 131
#define HPAD 132

typedef unsigned long long ull;

// ---------------------------------------------------------------------------
// Scratch (__device__ globals: allocation-free)
// ---------------------------------------------------------------------------
__device__ __align__(16) float g_w1q[33 * 128 * 4];  // [kq][o][4] permuted w1
__device__ __align__(16) float g_w2q[32 * 128 * 4];  // [kq][o][4] w2
__device__ int g_idx[BB * NN * 3];

// ---------------------------------------------------------------------------
// f32x2 helpers (FFMA2 is PTX-only)
// ---------------------------------------------------------------------------
__device__ __forceinline__ ull fma2(ull a, ull b, ull c) {
    ull d;
    asm("fma.rn.f32x2 %0, %1, %2, %3;" : "=l"(d) : "l"(a), "l"(b), "l"(c));
    return d;
}
__device__ __forceinline__ ull pack2(float a, float b) {
    ull r;
    asm("mov.b64 %0, {%1, %2};" : "=l"(r)
        : "r"(__float_as_uint(a)), "r"(__float_as_uint(b)));
    return r;
}
__device__ __forceinline__ float2 unpack2(ull v) {
    unsigned int lo, hi;
    asm("mov.b64 {%0, %1}, %2;" : "=r"(lo), "=r"(hi) : "l"(v));
    return make_float2(__uint_as_float(lo), __uint_as_float(hi));
}

// ---------------------------------------------------------------------------
// Kernel 1: kNN (blocks 0..255) + weight prep (blocks 256..385)
//   knn blocks: 64 threads, 4 queries/thread (256 queries/block),
//   sampled keys computed in-block from sx into SMEM (64KB)
// ---------------------------------------------------------------------------
#define KNN_BLOCKS 256
#define W1_W (33 * 128)
#define W2_W (32 * 128)
#define WPREP_ITEMS (W1_W + W2_W)          // 8320
#define WPREP_BLOCKS (WPREP_ITEMS / 64)    // 130

__global__ void __launch_bounds__(64) knn_prep_kernel(
    const float* __restrict__ x, const float* __restrict__ sx,
    const float* __restrict__ w1, const float* __restrict__ w2) {

    if (blockIdx.x >= KNN_BLOCKS) {
        // ---- weight prep path ----
        int i = (blockIdx.x - KNN_BLOCKS) * 64 + threadIdx.x;
        if (i < W1_W) {
            int kq = i >> 7, o = i & 127;
            float v[4];
#pragma unroll
            for (int q = 0; q < 4; q++) {
                int k = kq * 4 + q;
                if (k < 128)      v[q] = w1[o * INC + 3 + k];
                else if (k < 131) v[q] = w1[o * INC + (k - 128)];
                else              v[q] = 0.f;
            }
            *(float4*)&g_w1q[i * 4] = make_float4(v[0], v[1], v[2], v[3]);
        } else {
            int t = i - W1_W;
            int kq = t >> 7, o = t & 127;
            const float* wr = w2 + o * 128 + kq * 4;
            *(float4*)&g_w2q[t * 4] = make_float4(wr[0], wr[1], wr[2], wr[3]);
        }
        return;
    }

    // ---- knn path ----
    extern __shared__ float4 sm4[];
    float4* skA = sm4;        // (-2sx_j,-2sx_j1,-2sy_j,-2sy_j1)  32KB
    float4* skB = sm4 + M2;   // (-2sz_j,-2sz_j1,|s_j|^2,|s_j1|^2) 32KB

    const int q0 = blockIdx.x * 256;
    const int b  = q0 / NN;
    const int tid = threadIdx.x;

    // build paired keys from sx
    const float* sxb = sx + (size_t)b * MM * 3;
    for (int j2 = tid; j2 < M2; j2 += 64) {
        const float* p = sxb + (size_t)j2 * 6;
        float a0 = p[0], a1 = p[1], a2 = p[2];
        float c0 = p[3], c1 = p[4], c2 = p[5];
        skA[j2] = make_float4(-2.f * a0, -2.f * c0, -2.f * a1, -2.f * c1);
        skB[j2] = make_float4(-2.f * a2, -2.f * c2,
                              a0 * a0 + a1 * a1 + a2 * a2,
                              c0 * c0 + c1 * c1 + c2 * c2);
    }
    __syncthreads();

    // 4 queries per thread (interleaved for coalesced x loads)
    int   qv[4];
    ull   x00[4], x11[4], x22[4];
    float m0[4], m1[4], m2v[4];
    int   i0[4], i1[4], i2[4];
#pragma unroll
    for (int v = 0; v < 4; v++) {
        int q = q0 + tid + 64 * v;
        qv[v] = q;
        float c0 = x[q * 3 + 0], c1 = x[q * 3 + 1], c2 = x[q * 3 + 2];
        x00[v] = pack2(c0, c0);
        x11[v] = pack2(c1, c1);
        x22[v] = pack2(c2, c2);
        m0[v] = CUDART_INF_F; m1[v] = CUDART_INF_F; m2v[v] = CUDART_INF_F;
        i0[v] = 0; i1[v] = 0; i2[v] = 0;
    }

    const ulonglong2* A2 = (const ulonglong2*)skA;
    const ulonglong2* B2 = (const ulonglong2*)skB;

#pragma unroll 2
    for (int j2 = 0; j2 < M2; j2++) {
        ulonglong2 A  = A2[j2];
        ulonglong2 Bv = B2[j2];
#pragma unroll
        for (int v = 0; v < 4; v++) {
            ull d = fma2(Bv.x, x22[v], Bv.y);
            d = fma2(A.y, x11[v], d);
            d = fma2(A.x, x00[v], d);
            float2 vv = unpack2(d);
            if (fminf(vv.x, vv.y) < m2v[v]) {   // rare
                if (vv.x < m2v[v]) {
                    float t = vv.x; int j = 2 * j2;
                    if (t < m1[v]) {
                        m2v[v] = m1[v]; i2[v] = i1[v];
                        if (t < m0[v]) { m1[v] = m0[v]; i1[v] = i0[v]; m0[v] = t; i0[v] = j; }
                        else           { m1[v] = t;     i1[v] = j; }
                    } else { m2v[v] = t; i2[v] = j; }
                }
                if (vv.y < m2v[v]) {
                    float t = vv.y; int j = 2 * j2 + 1;
                    if (t < m1[v]) {
                        m2v[v] = m1[v]; i2[v] = i1[v];
                        if (t < m0[v]) { m1[v] = m0[v]; i1[v] = i0[v]; m0[v] = t; i0[v] = j; }
                        else           { m1[v] = t;     i1[v] = j; }
                    } else { m2v[v] = t; i2[v] = j; }
                }
            }
        }
    }

#pragma unroll
    for (int v = 0; v < 4; v++) {
        g_idx[qv[v] * 3 + 0] = i0[v];
        g_idx[qv[v] * 3 + 1] = i1[v];
        g_idx[qv[v] * 3 + 2] = i2[v];
    }
}

// ---------------------------------------------------------------------------
// Kernel 2: fused gather + MLP, 512 threads, 64-point tile
//   thread = (o = tid&127, point-group pg = tid>>7 of 16 points)
//   acc[16] f32x2 -> ~32 accumulator regs, no spill
// ---------------------------------------------------------------------------
__global__ void __launch_bounds__(512) mlp_kernel(
    const float* __restrict__ x, const float* __restrict__ feat,
    const float* __restrict__ b1, const float* __restrict__ b2,
    float* __restrict__ out) {
    extern __shared__ float sm[];
    float* hs = sm;               // [64][132]
    float* t1 = sm + 64 * HPAD;   // [64][132]

    const int tid = threadIdx.x;
    const int o   = tid & 127;
    const int pg  = tid >> 7;
    const int pb  = pg * 16;
    const int p0  = blockIdx.x * 64;
    const int b   = p0 / NN;
    const int n0  = p0 - b * NN;

    // ---- gather: 16 warps x 4 points, lane = float4 channel chunk ----
    {
        const int wid  = tid >> 5;
        const int lane = tid & 31;
        const float4* F = (const float4*)feat;
#pragma unroll
        for (int t = 0; t < 4; t++) {
            const int pt = wid * 4 + t;
            const int gq = p0 + pt;
            const int j0 = g_idx[gq * 3 + 0];
            const int j1 = g_idx[gq * 3 + 1];
            const int j2 = g_idx[gq * 3 + 2];
            float4 f0 = F[(size_t)(b * MM + j0) * 32 + lane];
            float4 f1 = F[(size_t)(b * MM + j1) * 32 + lane];
            float4 f2 = F[(size_t)(b * MM + j2) * 32 + lane];
            float4 a;
            a.x = (f0.x + f1.x + f2.x) * (1.f / 3.f);
            a.y = (f0.y + f1.y + f2.y) * (1.f / 3.f);
            a.z = (f0.z + f1.z + f2.z) * (1.f / 3.f);
            a.w = (f0.w + f1.w + f2.w) * (1.f / 3.f);
            *(float4*)&hs[pt * HPAD + lane * 4] = a;
            if (lane == 0) {
                *(float4*)&hs[pt * HPAD + 128] =
                    make_float4(x[gq * 3 + 0], x[gq * 3 + 1], x[gq * 3 + 2], 0.f);
            }
        }
    }
    __syncthreads();

    ull acc[16];

    // ---- stage 1: t1 = relu(h @ w1^T + b1) ----
    {
#pragma unroll
        for (int p = 0; p < 16; p++) acc[p] = 0ull;
        const ulonglong2* w1q = (const ulonglong2*)g_w1q;
        for (int kq = 0; kq < 33; kq++) {
            ulonglong2 w = w1q[kq * 128 + o];           // coalesced LDG.128
            const float* hrow = hs + pb * HPAD + kq * 4;
#pragma unroll
            for (int p = 0; p < 16; p++) {
                ulonglong2 h = *(const ulonglong2*)(hrow + p * HPAD);
                acc[p] = fma2(w.x, h.x, acc[p]);
                acc[p] = fma2(w.y, h.y, acc[p]);
            }
        }
        const float bias = b1[o];
#pragma unroll
        for (int p = 0; p < 16; p++) {
            float2 s = unpack2(acc[p]);
            t1[(pb + p) * HPAD + o] = fmaxf(s.x + s.y + bias, 0.f);
        }
    }
    __syncthreads();

    // ---- stage 2: out = t1 @ w2^T + b2 ----
    {
#pragma unroll
        for (int p = 0; p < 16; p++) acc[p] = 0ull;
        const ulonglong2* w2q = (const ulonglong2*)g_w2q;
        for (int kq = 0; kq < 32; kq++) {
            ulonglong2 w = w2q[kq * 128 + o];
            const float* trow = t1 + pb * HPAD + kq * 4;
#pragma unroll
            for (int p = 0; p < 16; p++) {
                ulonglong2 h = *(const ulonglong2*)(trow + p * HPAD);
                acc[p] = fma2(w.x, h.x, acc[p]);
                acc[p] = fma2(w.y, h.y, acc[p]);
            }
        }
        const float bias = b2[o];
        float* s_o = hs;   // reuse, stride 129 (conflict-free transpose)
#pragma unroll
        for (int p = 0; p < 16; p++) {
            float2 s = unpack2(acc[p]);
            s_o[(pb + p) * 129 + o] = s.x + s.y + bias;
        }
    }
    __syncthreads();

    // ---- coalesced transposed store: out[b][oc][n0+p] ----
    {
        const float* s_o = hs;
        float* ob = out + (size_t)b * OUTC * NN + n0;
        for (int idx = tid; idx < 128 * 64; idx += 512) {
            const int oc = idx >> 6;
            const int p  = idx & 63;
            ob[(size_t)oc * NN + p] = s_o[p * 129 + oc];
        }
    }
}

// ---------------------------------------------------------------------------
extern "C" void kernel_launch(void* const* d_in, const int* in_sizes, int n_in,
                              void* d_out, int out_size) {
    const float* x   = (const float*)d_in[0];
    const float* sx  = (const float*)d_in[1];
    const float* ft  = (const float*)d_in[2];
    const float* w1  = (const float*)d_in[3];
    const float* b1  = (const float*)d_in[4];
    const float* w2  = (const float*)d_in[5];
    const float* b2  = (const float*)d_in[6];
    float* out = (float*)d_out;

    const int knn_smem = MM * sizeof(float4);            // 64 KB
    const int mlp_smem = 2 * 64 * HPAD * sizeof(float);  // 67.6 KB

    cudaFuncSetAttribute(knn_prep_kernel,
                         cudaFuncAttributeMaxDynamicSharedMemorySize, knn_smem);
    cudaFuncSetAttribute(mlp_kernel,
                         cudaFuncAttributeMaxDynamicSharedMemorySize, mlp_smem);

    knn_prep_kernel<<<KNN_BLOCKS + WPREP_BLOCKS, 64, knn_smem>>>(x, sx, w1, w2);
    mlp_kernel<<<(BB * NN) / 64, 512, mlp_smem>>>(x, ft, b1, b2, out);
}

// round 4
// speedup vs baseline: 1.5039x; 1.5039x over previous
#include <cuda_runtime.h>
#include <math_constants.h>

#define BB 2
#define NN 32768
#define MM 4096
#define M2 (MM / 2)
#define CC 128
#define OUTC 128
#define INC 131
#define HPAD 132

typedef unsigned long long ull;

// ---------------------------------------------------------------------------
// Scratch (__device__ globals: allocation-free)
// ---------------------------------------------------------------------------
__device__ __align__(16) float g_w1q[33 * 128 * 4];  // [kq][o][4] permuted w1
__device__ __align__(16) float g_w2q[32 * 128 * 4];  // [kq][o][4] w2
__device__ int g_idx[BB * NN * 3];

// ---------------------------------------------------------------------------
// f32x2 helpers (FFMA2 is PTX-only)
// ---------------------------------------------------------------------------
__device__ __forceinline__ ull fma2(ull a, ull b, ull c) {
    ull d;
    asm("fma.rn.f32x2 %0, %1, %2, %3;" : "=l"(d) : "l"(a), "l"(b), "l"(c));
    return d;
}
__device__ __forceinline__ ull pack2(float a, float b) {
    ull r;
    asm("mov.b64 %0, {%1, %2};" : "=l"(r)
        : "r"(__float_as_uint(a)), "r"(__float_as_uint(b)));
    return r;
}
__device__ __forceinline__ float2 unpack2(ull v) {
    unsigned int lo, hi;
    asm("mov.b64 {%0, %1}, %2;" : "=r"(lo), "=r"(hi) : "l"(v));
    return make_float2(__uint_as_float(lo), __uint_as_float(hi));
}

// ---------------------------------------------------------------------------
// Kernel 1: kNN (blocks 0..255) + weight prep (blocks 256..320)
//   knn blocks: 128 threads, 2 queries/thread (256 queries/block)
// ---------------------------------------------------------------------------
#define KNN_BLOCKS 256
#define W1_W (33 * 128)
#define W2_W (32 * 128)
#define WPREP_ITEMS (W1_W + W2_W)           // 8320
#define WPREP_BLOCKS (WPREP_ITEMS / 128)    // 65

__global__ void __launch_bounds__(128) knn_prep_kernel(
    const float* __restrict__ x, const float* __restrict__ sx,
    const float* __restrict__ w1, const float* __restrict__ w2) {

    if (blockIdx.x >= KNN_BLOCKS) {
        // ---- weight prep path ----
        int i = (blockIdx.x - KNN_BLOCKS) * 128 + threadIdx.x;
        if (i < W1_W) {
            int kq = i >> 7, o = i & 127;
            float v[4];
#pragma unroll
            for (int q = 0; q < 4; q++) {
                int k = kq * 4 + q;
                if (k < 128)      v[q] = w1[o * INC + 3 + k];
                else if (k < 131) v[q] = w1[o * INC + (k - 128)];
                else              v[q] = 0.f;
            }
            *(float4*)&g_w1q[i * 4] = make_float4(v[0], v[1], v[2], v[3]);
        } else {
            int t = i - W1_W;
            int kq = t >> 7, o = t & 127;
            const float* wr = w2 + o * 128 + kq * 4;
            *(float4*)&g_w2q[t * 4] = make_float4(wr[0], wr[1], wr[2], wr[3]);
        }
        return;
    }

    // ---- knn path ----
    extern __shared__ float4 sm4[];
    float4* skA = sm4;        // (-2sx_j,-2sx_j1,-2sy_j,-2sy_j1)  32KB
    float4* skB = sm4 + M2;   // (-2sz_j,-2sz_j1,|s_j|^2,|s_j1|^2) 32KB

    const int q0  = blockIdx.x * 256;
    const int b   = q0 / NN;
    const int tid = threadIdx.x;

    // build paired keys from sx
    const float* sxb = sx + (size_t)b * MM * 3;
    for (int j2 = tid; j2 < M2; j2 += 128) {
        const float* p = sxb + (size_t)j2 * 6;
        float a0 = p[0], a1 = p[1], a2 = p[2];
        float c0 = p[3], c1 = p[4], c2 = p[5];
        skA[j2] = make_float4(-2.f * a0, -2.f * c0, -2.f * a1, -2.f * c1);
        skB[j2] = make_float4(-2.f * a2, -2.f * c2,
                              a0 * a0 + a1 * a1 + a2 * a2,
                              c0 * c0 + c1 * c1 + c2 * c2);
    }
    __syncthreads();

    // 2 queries per thread
    const int qa = q0 + tid;
    const int qb = q0 + 128 + tid;
    float a0c = x[qa * 3 + 0], a1c = x[qa * 3 + 1], a2c = x[qa * 3 + 2];
    float b0c = x[qb * 3 + 0], b1c = x[qb * 3 + 1], b2c = x[qb * 3 + 2];
    const ull ax0 = pack2(a0c, a0c), ax1 = pack2(a1c, a1c), ax2 = pack2(a2c, a2c);
    const ull bx0 = pack2(b0c, b0c), bx1 = pack2(b1c, b1c), bx2 = pack2(b2c, b2c);

    float am0 = CUDART_INF_F, am1 = CUDART_INF_F, am2 = CUDART_INF_F;
    float bm0 = CUDART_INF_F, bm1 = CUDART_INF_F, bm2 = CUDART_INF_F;
    int   ai0 = 0, ai1 = 0, ai2 = 0, bi0 = 0, bi1 = 0, bi2 = 0;

    const ulonglong2* A2 = (const ulonglong2*)skA;
    const ulonglong2* B2 = (const ulonglong2*)skB;

#pragma unroll 2
    for (int j2 = 0; j2 < M2; j2++) {
        ulonglong2 A  = A2[j2];
        ulonglong2 Bv = B2[j2];

        ull da = fma2(Bv.x, ax2, Bv.y);
        da = fma2(A.y, ax1, da);
        da = fma2(A.x, ax0, da);
        ull db = fma2(Bv.x, bx2, Bv.y);
        db = fma2(A.y, bx1, db);
        db = fma2(A.x, bx0, db);

        float2 va = unpack2(da);
        float2 vb = unpack2(db);

        if (fminf(va.x, va.y) < am2) {
            if (va.x < am2) {
                float t = va.x; int j = 2 * j2;
                if (t < am1) {
                    am2 = am1; ai2 = ai1;
                    if (t < am0) { am1 = am0; ai1 = ai0; am0 = t; ai0 = j; }
                    else         { am1 = t;   ai1 = j; }
                } else { am2 = t; ai2 = j; }
            }
            if (va.y < am2) {
                float t = va.y; int j = 2 * j2 + 1;
                if (t < am1) {
                    am2 = am1; ai2 = ai1;
                    if (t < am0) { am1 = am0; ai1 = ai0; am0 = t; ai0 = j; }
                    else         { am1 = t;   ai1 = j; }
                } else { am2 = t; ai2 = j; }
            }
        }
        if (fminf(vb.x, vb.y) < bm2) {
            if (vb.x < bm2) {
                float t = vb.x; int j = 2 * j2;
                if (t < bm1) {
                    bm2 = bm1; bi2 = bi1;
                    if (t < bm0) { bm1 = bm0; bi1 = bi0; bm0 = t; bi0 = j; }
                    else         { bm1 = t;   bi1 = j; }
                } else { bm2 = t; bi2 = j; }
            }
            if (vb.y < bm2) {
                float t = vb.y; int j = 2 * j2 + 1;
                if (t < bm1) {
                    bm2 = bm1; bi2 = bi1;
                    if (t < bm0) { bm1 = bm0; bi1 = bi0; bm0 = t; bi0 = j; }
                    else         { bm1 = t;   bi1 = j; }
                } else { bm2 = t; bi2 = j; }
            }
        }
    }

    g_idx[qa * 3 + 0] = ai0; g_idx[qa * 3 + 1] = ai1; g_idx[qa * 3 + 2] = ai2;
    g_idx[qb * 3 + 0] = bi0; g_idx[qb * 3 + 1] = bi1; g_idx[qb * 3 + 2] = bi2;
}

// ---------------------------------------------------------------------------
// Kernel 2: fused gather + MLP, 512 threads, 64-point tile
//   thread = (oc2 = tid&63 -> out channels {oc2, oc2+64}, pg = tid>>6 -> 8 pts)
//   h LDS is warp-uniform (broadcast) and reused by 2 out channels
// ---------------------------------------------------------------------------
__global__ void __launch_bounds__(512, 2) mlp_kernel(
    const float* __restrict__ x, const float* __restrict__ feat,
    const float* __restrict__ b1, const float* __restrict__ b2,
    float* __restrict__ out) {
    extern __shared__ float sm[];
    float* hs = sm;               // [64][132]
    float* t1 = sm + 64 * HPAD;   // [64][132]

    const int tid = threadIdx.x;
    const int oc2 = tid & 63;     // output channels oc2, oc2+64
    const int pg  = tid >> 6;     // 8 point-groups of 8
    const int pb  = pg * 8;
    const int p0  = blockIdx.x * 64;
    const int b   = p0 / NN;
    const int n0  = p0 - b * NN;

    // ---- gather: 16 warps x 4 points, lane = float4 channel chunk ----
    {
        const int wid  = tid >> 5;
        const int lane = tid & 31;
        const float4* F = (const float4*)feat;
#pragma unroll
        for (int t = 0; t < 4; t++) {
            const int pt = wid * 4 + t;
            const int gq = p0 + pt;
            const int j0 = g_idx[gq * 3 + 0];
            const int j1 = g_idx[gq * 3 + 1];
            const int j2 = g_idx[gq * 3 + 2];
            float4 f0 = F[(size_t)(b * MM + j0) * 32 + lane];
            float4 f1 = F[(size_t)(b * MM + j1) * 32 + lane];
            float4 f2 = F[(size_t)(b * MM + j2) * 32 + lane];
            float4 a;
            a.x = (f0.x + f1.x + f2.x) * (1.f / 3.f);
            a.y = (f0.y + f1.y + f2.y) * (1.f / 3.f);
            a.z = (f0.z + f1.z + f2.z) * (1.f / 3.f);
            a.w = (f0.w + f1.w + f2.w) * (1.f / 3.f);
            *(float4*)&hs[pt * HPAD + lane * 4] = a;
            if (lane == 0) {
                *(float4*)&hs[pt * HPAD + 128] =
                    make_float4(x[gq * 3 + 0], x[gq * 3 + 1], x[gq * 3 + 2], 0.f);
            }
        }
    }
    __syncthreads();

    ull accA[8], accB[8];

    // ---- stage 1: t1 = relu(h @ w1^T + b1) ----
    {
#pragma unroll
        for (int p = 0; p < 8; p++) { accA[p] = 0ull; accB[p] = 0ull; }
        const ulonglong2* w1q = (const ulonglong2*)g_w1q;
        for (int kq = 0; kq < 33; kq++) {
            ulonglong2 wA = w1q[kq * 128 + oc2];        // coalesced LDG.128
            ulonglong2 wB = w1q[kq * 128 + oc2 + 64];
            const float* hrow = hs + pb * HPAD + kq * 4;
#pragma unroll
            for (int p = 0; p < 8; p++) {
                ulonglong2 h = *(const ulonglong2*)(hrow + p * HPAD);  // broadcast
                accA[p] = fma2(wA.x, h.x, accA[p]);
                accA[p] = fma2(wA.y, h.y, accA[p]);
                accB[p] = fma2(wB.x, h.x, accB[p]);
                accB[p] = fma2(wB.y, h.y, accB[p]);
            }
        }
        const float biasA = b1[oc2];
        const float biasB = b1[oc2 + 64];
#pragma unroll
        for (int p = 0; p < 8; p++) {
            float2 sA = unpack2(accA[p]);
            float2 sB = unpack2(accB[p]);
            t1[(pb + p) * HPAD + oc2]      = fmaxf(sA.x + sA.y + biasA, 0.f);
            t1[(pb + p) * HPAD + oc2 + 64] = fmaxf(sB.x + sB.y + biasB, 0.f);
        }
    }
    __syncthreads();

    // ---- stage 2: out = t1 @ w2^T + b2 ----
    {
#pragma unroll
        for (int p = 0; p < 8; p++) { accA[p] = 0ull; accB[p] = 0ull; }
        const ulonglong2* w2q = (const ulonglong2*)g_w2q;
        for (int kq = 0; kq < 32; kq++) {
            ulonglong2 wA = w2q[kq * 128 + oc2];
            ulonglong2 wB = w2q[kq * 128 + oc2 + 64];
            const float* trow = t1 + pb * HPAD + kq * 4;
#pragma unroll
            for (int p = 0; p < 8; p++) {
                ulonglong2 h = *(const ulonglong2*)(trow + p * HPAD);
                accA[p] = fma2(wA.x, h.x, accA[p]);
                accA[p] = fma2(wA.y, h.y, accA[p]);
                accB[p] = fma2(wB.x, h.x, accB[p]);
                accB[p] = fma2(wB.y, h.y, accB[p]);
            }
        }
        const float biasA = b2[oc2];
        const float biasB = b2[oc2 + 64];
        float* s_o = hs;   // reuse, stride 129 (conflict-free transpose)
#pragma unroll
        for (int p = 0; p < 8; p++) {
            float2 sA = unpack2(accA[p]);
            float2 sB = unpack2(accB[p]);
            s_o[(pb + p) * 129 + oc2]      = sA.x + sA.y + biasA;
            s_o[(pb + p) * 129 + oc2 + 64] = sB.x + sB.y + biasB;
        }
    }
    __syncthreads();

    // ---- coalesced transposed store: out[b][oc][n0+p] ----
    {
        const float* s_o = hs;
        float* ob = out + (size_t)b * OUTC * NN + n0;
        for (int idx = tid; idx < 128 * 64; idx += 512) {
            const int oc = idx >> 6;
            const int p  = idx & 63;
            ob[(size_t)oc * NN + p] = s_o[p * 129 + oc];
        }
    }
}

// ---------------------------------------------------------------------------
extern "C" void kernel_launch(void* const* d_in, const int* in_sizes, int n_in,
                              void* d_out, int out_size) {
    const float* x   = (const float*)d_in[0];
    const float* sx  = (const float*)d_in[1];
    const float* ft  = (const float*)d_in[2];
    const float* w1  = (const float*)d_in[3];
    const float* b1  = (const float*)d_in[4];
    const float* w2  = (const float*)d_in[5];
    const float* b2  = (const float*)d_in[6];
    float* out = (float*)d_out;

    const int knn_smem = MM * sizeof(float4);            // 64 KB
    const int mlp_smem = 2 * 64 * HPAD * sizeof(float);  // 67.6 KB

    cudaFuncSetAttribute(knn_prep_kernel,
                         cudaFuncAttributeMaxDynamicSharedMemorySize, knn_smem);
    cudaFuncSetAttribute(mlp_kernel,
                         cudaFuncAttributeMaxDynamicSharedMemorySize, mlp_smem);

    knn_prep_kernel<<<KNN_BLOCKS + WPREP_BLOCKS, 128, knn_smem>>>(x, sx, w1, w2);
    mlp_kernel<<<(BB * NN) / 64, 512, mlp_smem>>>(x, ft, b1, b2, out);
}

// round 5
// speedup vs baseline: 1.6430x; 1.0925x over previous
#include <cuda_runtime.h>
#include <math_constants.h>

#define BB 2
#define NN 32768
#define MM 4096
#define M2 (MM / 2)
#define CC 128
#define OUTC 128
#define INC 131
#define HPAD 132

typedef unsigned long long ull;

// ---------------------------------------------------------------------------
// Scratch (__device__ globals: allocation-free)
// ---------------------------------------------------------------------------
__device__ __align__(16) float g_w1q[33 * 128 * 4];  // [kq][o][4] permuted w1
__device__ __align__(16) float g_w2q[32 * 128 * 4];  // [kq][o][4] w2
__device__ int g_idx[BB * NN * 3];

// ---------------------------------------------------------------------------
// f32x2 helpers (FFMA2 is PTX-only)
// ---------------------------------------------------------------------------
__device__ __forceinline__ ull fma2(ull a, ull b, ull c) {
    ull d;
    asm("fma.rn.f32x2 %0, %1, %2, %3;" : "=l"(d) : "l"(a), "l"(b), "l"(c));
    return d;
}
__device__ __forceinline__ ull pack2(float a, float b) {
    ull r;
    asm("mov.b64 %0, {%1, %2};" : "=l"(r)
        : "r"(__float_as_uint(a)), "r"(__float_as_uint(b)));
    return r;
}
__device__ __forceinline__ float2 unpack2(ull v) {
    unsigned int lo, hi;
    asm("mov.b64 {%0, %1}, %2;" : "=r"(lo), "=r"(hi) : "l"(v));
    return make_float2(__uint_as_float(lo), __uint_as_float(hi));
}

// strict-< top-3 insertion (preserves jax top_k tie semantics)
#define INSERT3(val, jj, m0, m1, m2, i0, i1, i2)                    \
    do {                                                            \
        float _t = (val); int _j = (jj);                            \
        if (_t < m2) {                                              \
            if (_t < m1) {                                          \
                m2 = m1; i2 = i1;                                   \
                if (_t < m0) { m1 = m0; i1 = i0; m0 = _t; i0 = _j; }\
                else         { m1 = _t; i1 = _j; }                  \
            } else { m2 = _t; i2 = _j; }                            \
        }                                                           \
    } while (0)

// ---------------------------------------------------------------------------
// Kernel 1: kNN (blocks 0..255) + weight prep (blocks 256..320)
//   knn blocks: 128 threads, 2 queries/thread (256 queries/block)
//   hot loop: chunks of 8 j2-pairs (16 candidates), ONE screened branch/chunk
// ---------------------------------------------------------------------------
#define KNN_BLOCKS 256
#define W1_W (33 * 128)
#define W2_W (32 * 128)
#define WPREP_ITEMS (W1_W + W2_W)           // 8320
#define WPREP_BLOCKS (WPREP_ITEMS / 128)    // 65

__global__ void __launch_bounds__(128) knn_prep_kernel(
    const float* __restrict__ x, const float* __restrict__ sx,
    const float* __restrict__ w1, const float* __restrict__ w2) {

    if (blockIdx.x >= KNN_BLOCKS) {
        // ---- weight prep path ----
        int i = (blockIdx.x - KNN_BLOCKS) * 128 + threadIdx.x;
        if (i < W1_W) {
            int kq = i >> 7, o = i & 127;
            float v[4];
#pragma unroll
            for (int q = 0; q < 4; q++) {
                int k = kq * 4 + q;
                if (k < 128)      v[q] = w1[o * INC + 3 + k];
                else if (k < 131) v[q] = w1[o * INC + (k - 128)];
                else              v[q] = 0.f;
            }
            *(float4*)&g_w1q[i * 4] = make_float4(v[0], v[1], v[2], v[3]);
        } else {
            int t = i - W1_W;
            int kq = t >> 7, o = t & 127;
            const float* wr = w2 + o * 128 + kq * 4;
            *(float4*)&g_w2q[t * 4] = make_float4(wr[0], wr[1], wr[2], wr[3]);
        }
        return;
    }

    // ---- knn path ----
    extern __shared__ float4 sm4[];
    float4* skA = sm4;        // (-2sx_j,-2sx_j1,-2sy_j,-2sy_j1)  32KB
    float4* skB = sm4 + M2;   // (-2sz_j,-2sz_j1,|s_j|^2,|s_j1|^2) 32KB

    const int q0  = blockIdx.x * 256;
    const int b   = q0 / NN;
    const int tid = threadIdx.x;

    // build paired keys from sx
    const float* sxb = sx + (size_t)b * MM * 3;
    for (int j2 = tid; j2 < M2; j2 += 128) {
        const float* p = sxb + (size_t)j2 * 6;
        float a0 = p[0], a1 = p[1], a2 = p[2];
        float c0 = p[3], c1 = p[4], c2 = p[5];
        skA[j2] = make_float4(-2.f * a0, -2.f * c0, -2.f * a1, -2.f * c1);
        skB[j2] = make_float4(-2.f * a2, -2.f * c2,
                              a0 * a0 + a1 * a1 + a2 * a2,
                              c0 * c0 + c1 * c1 + c2 * c2);
    }
    __syncthreads();

    // 2 queries per thread
    const int qa = q0 + tid;
    const int qb = q0 + 128 + tid;
    float a0c = x[qa * 3 + 0], a1c = x[qa * 3 + 1], a2c = x[qa * 3 + 2];
    float b0c = x[qb * 3 + 0], b1c = x[qb * 3 + 1], b2c = x[qb * 3 + 2];
    const ull ax0 = pack2(a0c, a0c), ax1 = pack2(a1c, a1c), ax2 = pack2(a2c, a2c);
    const ull bx0 = pack2(b0c, b0c), bx1 = pack2(b1c, b1c), bx2 = pack2(b2c, b2c);

    float am0 = CUDART_INF_F, am1 = CUDART_INF_F, am2 = CUDART_INF_F;
    float bm0 = CUDART_INF_F, bm1 = CUDART_INF_F, bm2 = CUDART_INF_F;
    int   ai0 = 0, ai1 = 0, ai2 = 0, bi0 = 0, bi1 = 0, bi2 = 0;

    const ulonglong2* A2 = (const ulonglong2*)skA;
    const ulonglong2* B2 = (const ulonglong2*)skB;

#pragma unroll 1
    for (int jc = 0; jc < M2; jc += 8) {
        float2 va[8], vb[8];
        float cma = CUDART_INF_F, cmb = CUDART_INF_F;
#pragma unroll
        for (int u = 0; u < 8; u++) {
            ulonglong2 A  = A2[jc + u];
            ulonglong2 Bv = B2[jc + u];
            ull da = fma2(Bv.x, ax2, Bv.y);
            da = fma2(A.y, ax1, da);
            da = fma2(A.x, ax0, da);
            va[u] = unpack2(da);
            cma = fminf(cma, fminf(va[u].x, va[u].y));
            ull db = fma2(Bv.x, bx2, Bv.y);
            db = fma2(A.y, bx1, db);
            db = fma2(A.x, bx0, db);
            vb[u] = unpack2(db);
            cmb = fminf(cmb, fminf(vb[u].x, vb[u].y));
        }
        if (cma < am2) {   // rare after warmup: one branch per 16 candidates
#pragma unroll
            for (int u = 0; u < 8; u++) {
                INSERT3(va[u].x, 2 * (jc + u),     am0, am1, am2, ai0, ai1, ai2);
                INSERT3(va[u].y, 2 * (jc + u) + 1, am0, am1, am2, ai0, ai1, ai2);
            }
        }
        if (cmb < bm2) {
#pragma unroll
            for (int u = 0; u < 8; u++) {
                INSERT3(vb[u].x, 2 * (jc + u),     bm0, bm1, bm2, bi0, bi1, bi2);
                INSERT3(vb[u].y, 2 * (jc + u) + 1, bm0, bm1, bm2, bi0, bi1, bi2);
            }
        }
    }

    g_idx[qa * 3 + 0] = ai0; g_idx[qa * 3 + 1] = ai1; g_idx[qa * 3 + 2] = ai2;
    g_idx[qb * 3 + 0] = bi0; g_idx[qb * 3 + 1] = bi1; g_idx[qb * 3 + 2] = bi2;
}

// ---------------------------------------------------------------------------
// Kernel 2: fused gather + MLP, 512 threads, 64-point tile (unchanged from R4)
// ---------------------------------------------------------------------------
__global__ void __launch_bounds__(512, 2) mlp_kernel(
    const float* __restrict__ x, const float* __restrict__ feat,
    const float* __restrict__ b1, const float* __restrict__ b2,
    float* __restrict__ out) {
    extern __shared__ float sm[];
    float* hs = sm;               // [64][132]
    float* t1 = sm + 64 * HPAD;   // [64][132]

    const int tid = threadIdx.x;
    const int oc2 = tid & 63;     // output channels oc2, oc2+64
    const int pg  = tid >> 6;     // 8 point-groups of 8
    const int pb  = pg * 8;
    const int p0  = blockIdx.x * 64;
    const int b   = p0 / NN;
    const int n0  = p0 - b * NN;

    // ---- gather: 16 warps x 4 points, lane = float4 channel chunk ----
    {
        const int wid  = tid >> 5;
        const int lane = tid & 31;
        const float4* F = (const float4*)feat;
#pragma unroll
        for (int t = 0; t < 4; t++) {
            const int pt = wid * 4 + t;
            const int gq = p0 + pt;
            const int j0 = g_idx[gq * 3 + 0];
            const int j1 = g_idx[gq * 3 + 1];
            const int j2 = g_idx[gq * 3 + 2];
            float4 f0 = F[(size_t)(b * MM + j0) * 32 + lane];
            float4 f1 = F[(size_t)(b * MM + j1) * 32 + lane];
            float4 f2 = F[(size_t)(b * MM + j2) * 32 + lane];
            float4 a;
            a.x = (f0.x + f1.x + f2.x) * (1.f / 3.f);
            a.y = (f0.y + f1.y + f2.y) * (1.f / 3.f);
            a.z = (f0.z + f1.z + f2.z) * (1.f / 3.f);
            a.w = (f0.w + f1.w + f2.w) * (1.f / 3.f);
            *(float4*)&hs[pt * HPAD + lane * 4] = a;
            if (lane == 0) {
                *(float4*)&hs[pt * HPAD + 128] =
                    make_float4(x[gq * 3 + 0], x[gq * 3 + 1], x[gq * 3 + 2], 0.f);
            }
        }
    }
    __syncthreads();

    ull accA[8], accB[8];

    // ---- stage 1: t1 = relu(h @ w1^T + b1) ----
    {
#pragma unroll
        for (int p = 0; p < 8; p++) { accA[p] = 0ull; accB[p] = 0ull; }
        const ulonglong2* w1q = (const ulonglong2*)g_w1q;
        for (int kq = 0; kq < 33; kq++) {
            ulonglong2 wA = w1q[kq * 128 + oc2];        // coalesced LDG.128
            ulonglong2 wB = w1q[kq * 128 + oc2 + 64];
            const float* hrow = hs + pb * HPAD + kq * 4;
#pragma unroll
            for (int p = 0; p < 8; p++) {
                ulonglong2 h = *(const ulonglong2*)(hrow + p * HPAD);  // broadcast
                accA[p] = fma2(wA.x, h.x, accA[p]);
                accA[p] = fma2(wA.y, h.y, accA[p]);
                accB[p] = fma2(wB.x, h.x, accB[p]);
                accB[p] = fma2(wB.y, h.y, accB[p]);
            }
        }
        const float biasA = b1[oc2];
        const float biasB = b1[oc2 + 64];
#pragma unroll
        for (int p = 0; p < 8; p++) {
            float2 sA = unpack2(accA[p]);
            float2 sB = unpack2(accB[p]);
            t1[(pb + p) * HPAD + oc2]      = fmaxf(sA.x + sA.y + biasA, 0.f);
            t1[(pb + p) * HPAD + oc2 + 64] = fmaxf(sB.x + sB.y + biasB, 0.f);
        }
    }
    __syncthreads();

    // ---- stage 2: out = t1 @ w2^T + b2 ----
    {
#pragma unroll
        for (int p = 0; p < 8; p++) { accA[p] = 0ull; accB[p] = 0ull; }
        const ulonglong2* w2q = (const ulonglong2*)g_w2q;
        for (int kq = 0; kq < 32; kq++) {
            ulonglong2 wA = w2q[kq * 128 + oc2];
            ulonglong2 wB = w2q[kq * 128 + oc2 + 64];
            const float* trow = t1 + pb * HPAD + kq * 4;
#pragma unroll
            for (int p = 0; p < 8; p++) {
                ulonglong2 h = *(const ulonglong2*)(trow + p * HPAD);
                accA[p] = fma2(wA.x, h.x, accA[p]);
                accA[p] = fma2(wA.y, h.y, accA[p]);
                accB[p] = fma2(wB.x, h.x, accB[p]);
                accB[p] = fma2(wB.y, h.y, accB[p]);
            }
        }
        const float biasA = b2[oc2];
        const float biasB = b2[oc2 + 64];
        float* s_o = hs;   // reuse, stride 129 (conflict-free transpose)
#pragma unroll
        for (int p = 0; p < 8; p++) {
            float2 sA = unpack2(accA[p]);
            float2 sB = unpack2(accB[p]);
            s_o[(pb + p) * 129 + oc2]      = sA.x + sA.y + biasA;
            s_o[(pb + p) * 129 + oc2 + 64] = sB.x + sB.y + biasB;
        }
    }
    __syncthreads();

    // ---- coalesced transposed store: out[b][oc][n0+p] ----
    {
        const float* s_o = hs;
        float* ob = out + (size_t)b * OUTC * NN + n0;
        for (int idx = tid; idx < 128 * 64; idx += 512) {
            const int oc = idx >> 6;
            const int p  = idx & 63;
            ob[(size_t)oc * NN + p] = s_o[p * 129 + oc];
        }
    }
}

// ---------------------------------------------------------------------------
extern "C" void kernel_launch(void* const* d_in, const int* in_sizes, int n_in,
                              void* d_out, int out_size) {
    const float* x   = (const float*)d_in[0];
    const float* sx  = (const float*)d_in[1];
    const float* ft  = (const float*)d_in[2];
    const float* w1  = (const float*)d_in[3];
    const float* b1  = (const float*)d_in[4];
    const float* w2  = (const float*)d_in[5];
    const float* b2  = (const float*)d_in[6];
    float* out = (float*)d_out;

    const int knn_smem = MM * sizeof(float4);            // 64 KB
    const int mlp_smem = 2 * 64 * HPAD * sizeof(float);  // 67.6 KB

    cudaFuncSetAttribute(knn_prep_kernel,
                         cudaFuncAttributeMaxDynamicSharedMemorySize, knn_smem);
    cudaFuncSetAttribute(mlp_kernel,
                         cudaFuncAttributeMaxDynamicSharedMemorySize, mlp_smem);

    knn_prep_kernel<<<KNN_BLOCKS + WPREP_BLOCKS, 128, knn_smem>>>(x, sx, w1, w2);
    mlp_kernel<<<(BB * NN) / 64, 512, mlp_smem>>>(x, ft, b1, b2, out);
}